// round 15
// baseline (speedup 1.0000x reference)
#include <cuda_runtime.h>
#include <math.h>
#include <stdint.h>

#define BB 16
#define NN 1024
#define NHEADS 4
#define FIN 64
#define NHID 64
#define NCLASS 32
#define LRA 0.2f
#define FULL 0xffffffffu

// ---------------- scratch (device globals; no allocs) ----------------
__device__ __align__(16) float d_Wh1T[NHEADS*BB*NHID*NN];  // [h,b][c][j] 16.8 MB (tf32)
__device__ float d_f1[NHEADS*BB*NN];
__device__ __align__(8)  float2 d_eac1[NHEADS*BB*NN];      // (e^f, e^{0.2f})
__device__ __align__(16) float4 d_gv1[NHEADS*BB*NN];       // (g, e^g, e^{0.2g}, 0)
__device__ __align__(16) float d_hcat[BB*NN*NHEADS*NHID];  // 16.8 MB
__device__ __align__(16) float d_Wh2T[BB*NCLASS*NN];       // [b][c][j] 2 MB (tf32)
__device__ float d_f2[BB*NN];
__device__ __align__(8)  float2 d_eac2[BB*NN];
__device__ __align__(16) float4 d_gv2[BB*NN];
__device__ unsigned d_adjT[BB*(NN/32)*NN];   // [b][word][i]  2 MB

__device__ __forceinline__ float to_tf32(float x) {
    uint32_t r; asm("cvt.rna.tf32.f32 %0, %1;" : "=r"(r) : "f"(x));
    return __uint_as_float(r);
}
__device__ __forceinline__ uint32_t to_tf32_u(float x) {
    uint32_t r; asm("cvt.rna.tf32.f32 %0, %1;" : "=r"(r) : "f"(x));
    return r;
}
__device__ __forceinline__ void mma_tf32_16x8x8(float* d, const uint32_t* a, const uint32_t* b) {
    asm volatile(
        "mma.sync.aligned.m16n8k8.row.col.f32.tf32.tf32.f32 "
        "{%0,%1,%2,%3}, {%4,%5,%6,%7}, {%8,%9}, {%0,%1,%2,%3};"
        : "+f"(d[0]), "+f"(d[1]), "+f"(d[2]), "+f"(d[3])
        : "r"(a[0]), "r"(a[1]), "r"(a[2]), "r"(a[3]), "r"(b[0]), "r"(b[1]));
}

// ---------------- 1) pack adjacency to transposed bitmask ----------------
__global__ void pack_adj_kernel(const int* __restrict__ adj) {
    int warp = (blockIdx.x * blockDim.x + threadIdx.x) >> 5;
    int lane = threadIdx.x & 31;
    if (warp >= BB*NN) return;
    const int* row = adj + (long long)warp * NN;
    int b = warp >> 10, i = warp & 1023;
    unsigned mym = 0;
#pragma unroll
    for (int wb = 0; wb < 4; wb++) {
        int v[8];
#pragma unroll
        for (int u = 0; u < 8; u++) v[u] = row[(wb*8 + u)*32 + lane];
#pragma unroll
        for (int u = 0; u < 8; u++) {
            unsigned m = __ballot_sync(FULL, v[u] > 0);
            if (lane == wb*8 + u) mym = m;
        }
    }
    d_adjT[(b*32 + lane)*NN + i] = mym;
}

// ---------------- 2) Wh1T = (x @ W_heads[h])^T;  f,g + exps ----------------
// grid (NN/64, BB, NHEADS), block 256
__global__ void whx1_kernel(const float* __restrict__ x,
                            const float* __restrict__ Wh,
                            const float* __restrict__ ah) {
    __shared__ __align__(16) float sW[FIN*NHID];   // 16 KB
    __shared__ float sX[64][FIN+1];                // 16.6 KB; reused as transpose buffer
    __shared__ float sA[2*NHID];
    int h = blockIdx.z, b = blockIdx.y, i0 = blockIdx.x*64;
    int tid = threadIdx.x;

    const float4* Wsrc = (const float4*)(Wh + (long long)h*FIN*NHID);
    float4* Wdst = (float4*)sW;
    for (int idx = tid; idx < FIN*NHID/4; idx += 256) Wdst[idx] = Wsrc[idx];
    if (tid < 2*NHID) sA[tid] = ah[h*2*NHID + tid];
    for (int idx = tid; idx < 64*FIN/4; idx += 256) {
        int r = idx >> 4, c4 = idx & 15;
        float4 v = *(const float4*)(x + (long long)(b*NN + i0 + r)*FIN + c4*4);
        sX[r][c4*4+0]=v.x; sX[r][c4*4+1]=v.y; sX[r][c4*4+2]=v.z; sX[r][c4*4+3]=v.w;
    }
    __syncthreads();

    int r = tid >> 2, ct = tid & 3, c0 = ct*16;
    float acc[16];
#pragma unroll
    for (int c = 0; c < 16; c++) acc[c] = 0.f;
#pragma unroll 4
    for (int k = 0; k < FIN; k++) {
        float xv = sX[r][k];
#pragma unroll
        for (int c4 = 0; c4 < 4; c4++) {
            float4 w = *(const float4*)(&sW[k*NHID + c0 + c4*4]);
            acc[c4*4+0] += xv*w.x; acc[c4*4+1] += xv*w.y;
            acc[c4*4+2] += xv*w.z; acc[c4*4+3] += xv*w.w;
        }
    }

    float pf = 0.f, pg = 0.f;
#pragma unroll
    for (int c = 0; c < 16; c++) { pf += acc[c]*sA[c0+c]; pg += acc[c]*sA[NHID+c0+c]; }
    pf += __shfl_xor_sync(FULL, pf, 1); pg += __shfl_xor_sync(FULL, pg, 1);
    pf += __shfl_xor_sync(FULL, pf, 2); pg += __shfl_xor_sync(FULL, pg, 2);
    if (ct == 0) {
        int o = (h*BB+b)*NN + i0 + r;
        d_f1[o] = pf;
        d_eac1[o] = make_float2(__expf(pf), __expf(LRA*pf));
        d_gv1[o] = make_float4(pg, __expf(pg), __expf(LRA*pg), 0.f);
    }

    __syncthreads();
#pragma unroll
    for (int c = 0; c < 16; c++) sX[c0 + c][r] = to_tf32(acc[c]);
    __syncthreads();
    float* WT = d_Wh1T + (long long)(h*BB + b)*NHID*NN;
    for (int idx = tid; idx < 64*16; idx += 256) {
        int c = idx >> 4, j4 = idx & 15;
        float4 v = make_float4(sX[c][j4*4], sX[c][j4*4+1], sX[c][j4*4+2], sX[c][j4*4+3]);
        *(float4*)(WT + (long long)c*NN + i0 + j4*4) = v;
    }
}

// ---------------- 3) PV layer-1 via mma.sync tf32 + ones-column row sums ----------------
// M-tile 128, 256 thr, 8 warps x 16 rows.
__global__ __launch_bounds__(256) void pv1_mma_kernel() {
    constexpr int F  = NHID;       // 64
    constexpr int MT = 128;
    constexpr int NT = F / 8;      // 8
    constexpr int NQ = 2;
    __shared__ float4 sGv[NN];
    __shared__ float  sF[MT];
    __shared__ float2 sEac[MT];
    __shared__ float  sBf[2][4][NT][32][2];
    __shared__ unsigned sAdj[2][MT];
    __shared__ float  sS[MT];

    const int tid = threadIdx.x, wid = tid >> 5, lane = tid & 31;
    const int g = lane >> 2, t = lane & 3;
    const int b = blockIdx.y, h = blockIdx.z, i0 = blockIdx.x * MT;
    const int hb = h*BB + b;
    const float* BT = d_Wh1T + (long long)hb*F*NN;

    for (int idx = tid; idx < NN; idx += 256) sGv[idx] = d_gv1[(long long)hb*NN + idx];
    if (tid < MT) {
        sF[tid]   = d_f1[(long long)hb*NN + i0 + tid];
        sEac[tid] = d_eac1[(long long)hb*NN + i0 + tid];
    }
    __syncthreads();

    float fr[2], ear[2], ecr[2];
#pragma unroll
    for (int r = 0; r < 2; r++) {
        int lr = wid*16 + g + 8*r;
        fr[r] = sF[lr]; ear[r] = sEac[lr].x; ecr[r] = sEac[lr].y;
    }

    float acc[NT][4], accS[4];
#pragma unroll
    for (int nt = 0; nt < NT; nt++)
#pragma unroll
        for (int c = 0; c < 4; c++) acc[nt][c] = 0.f;
#pragma unroll
    for (int c = 0; c < 4; c++) accS[c] = 0.f;
    uint32_t bone[2];
    bone[0] = bone[1] = (lane < 4) ? 0x3f800000u : 0u;

    const unsigned* adjTp = d_adjT + (long long)b*32*NN + i0 + tid;

    float4 breg[NQ];
#pragma unroll
    for (int q = 0; q < NQ; q++) {
        int idx = tid + 256*q; int n = idx >> 3, k4 = idx & 7;
        breg[q] = *(const float4*)(BT + (long long)n*NN + k4*4);
    }
    unsigned aw = (tid < MT) ? adjTp[0] : 0u;

#pragma unroll 1
    for (int chunk = 0; chunk < 32; chunk++) {
        const int buf = chunk & 1;
#pragma unroll
        for (int q = 0; q < NQ; q++) {
            int idx = tid + 256*q; int n = idx >> 3, k4 = idx & 7;
            int ks = k4 >> 1, bb = k4 & 1, nt = n >> 3, ln = (n & 7) * 4;
            sBf[buf][ks][nt][ln+0][bb] = breg[q].x;
            sBf[buf][ks][nt][ln+1][bb] = breg[q].y;
            sBf[buf][ks][nt][ln+2][bb] = breg[q].z;
            sBf[buf][ks][nt][ln+3][bb] = breg[q].w;
        }
        if (tid < MT) sAdj[buf][tid] = aw;
        __syncthreads();

        if (chunk < 31) {
#pragma unroll
            for (int q = 0; q < NQ; q++) {
                int idx = tid + 256*q; int n = idx >> 3, k4 = idx & 7;
                breg[q] = *(const float4*)(BT + (long long)n*NN + (chunk+1)*32 + k4*4);
            }
            if (tid < MT) aw = adjTp[(long long)(chunk+1)*NN];
        }

        unsigned wr[2];
        wr[0] = sAdj[buf][wid*16 + g];
        wr[1] = sAdj[buf][wid*16 + g + 8];

#pragma unroll
        for (int s = 0; s < 4; s++) {
            const float4 gva = sGv[chunk*32 + 8*s + t];
            const float4 gvb = sGv[chunk*32 + 8*s + t + 4];
            uint32_t afr[4];
#pragma unroll
            for (int half = 0; half < 2; half++) {
                float s0 = fr[half] + gva.x;
                float p0 = (s0 > 0.f ? ear[half] : ecr[half]) * (s0 > 0.f ? gva.y : gva.z);
                p0 = ((wr[half] >> (8*s + t)) & 1u) ? p0 : 0.f;
                float s1 = fr[half] + gvb.x;
                float p1 = (s1 > 0.f ? ear[half] : ecr[half]) * (s1 > 0.f ? gvb.y : gvb.z);
                p1 = ((wr[half] >> (8*s + t + 4)) & 1u) ? p1 : 0.f;
                afr[half]     = to_tf32_u(p0);
                afr[half + 2] = to_tf32_u(p1);
            }
#pragma unroll
            for (int nt = 0; nt < NT; nt++) {
                uint32_t bf[2];
                float2 bv = *(const float2*)&sBf[buf][s][nt][lane][0];
                bf[0] = __float_as_uint(bv.x); bf[1] = __float_as_uint(bv.y);
                mma_tf32_16x8x8(acc[nt], afr, bf);
            }
            mma_tf32_16x8x8(accS, afr, bone);
        }
    }

    if (t == 0) {
        sS[wid*16 + g]     = accS[0];
        sS[wid*16 + g + 8] = accS[2];
    }
    __syncthreads();

#pragma unroll
    for (int half = 0; half < 2; half++) {
        int lrow = wid*16 + g + 8*half;
        int grow = i0 + lrow;
        float isv = 1.0f / fmaxf(sS[lrow], 1e-30f);
#pragma unroll
        for (int nt = 0; nt < NT; nt++) {
            float v0 = acc[nt][half*2+0] * isv;
            float v1 = acc[nt][half*2+1] * isv;
            v0 = v0 > 0.f ? v0 : expm1f(v0);
            v1 = v1 > 0.f ? v1 : expm1f(v1);
            float* o = d_hcat + ((long long)(b*NN + grow))*(NHEADS*NHID) + h*NHID + nt*8 + t*2;
            *(float2*)o = make_float2(v0, v1);
        }
    }
}

// ---------------- 4) PV layer-2: 256 thr, split-N warp groups ----------------
// M-tile 64; 8 warps = 2 groups of 4; group wg owns n-tiles {2wg, 2wg+1}.
__global__ __launch_bounds__(256) void pv2_mma_kernel(float* __restrict__ dout) {
    constexpr int MT = 64;
    __shared__ float4 sGv[NN];                  // 16 KB
    __shared__ float  sF[MT];
    __shared__ float2 sEac[MT];
    __shared__ float  sBf[2][4][4][32][2];      // 8 KB
    __shared__ unsigned sAdj[2][MT];
    __shared__ float  sS[MT];

    const int tid = threadIdx.x, wid = tid >> 5, lane = tid & 31;
    const int g = lane >> 2, t = lane & 3;
    const int wg = wid >> 2, wl = wid & 3;
    const int b = blockIdx.y, i0 = blockIdx.x * MT;

    for (int idx = tid; idx < NN; idx += 256) sGv[idx] = d_gv2[(long long)b*NN + idx];
    if (tid < MT) {
        sF[tid]   = d_f2[(long long)b*NN + i0 + tid];
        sEac[tid] = d_eac2[(long long)b*NN + i0 + tid];
    }
    __syncthreads();

    float fr[2], ear[2], ecr[2];
#pragma unroll
    for (int r = 0; r < 2; r++) {
        int lr = wl*16 + g + 8*r;
        fr[r] = sF[lr]; ear[r] = sEac[lr].x; ecr[r] = sEac[lr].y;
    }

    float acc[2][4], accS[4];
#pragma unroll
    for (int j = 0; j < 2; j++)
#pragma unroll
        for (int c = 0; c < 4; c++) acc[j][c] = 0.f;
#pragma unroll
    for (int c = 0; c < 4; c++) accS[c] = 0.f;
    uint32_t bone[2];
    bone[0] = bone[1] = (lane < 4) ? 0x3f800000u : 0u;

    const float* BT = d_Wh2T + (long long)b*NCLASS*NN;
    const unsigned* adjTp = d_adjT + (long long)b*32*NN + i0 + tid;

    // prefetch chunk 0 (1 float4 per thread covers 32n x 32k)
    float4 breg;
    {
        int n = tid >> 3, k4 = tid & 7;
        breg = *(const float4*)(BT + (long long)n*NN + k4*4);
    }
    unsigned aw = (tid < MT) ? adjTp[0] : 0u;

#pragma unroll 1
    for (int chunk = 0; chunk < 32; chunk++) {
        const int buf = chunk & 1;
        {
            int n = tid >> 3, k4 = tid & 7;
            int ks = k4 >> 1, bb = k4 & 1, nt = n >> 3, ln = (n & 7) * 4;
            sBf[buf][ks][nt][ln+0][bb] = breg.x;
            sBf[buf][ks][nt][ln+1][bb] = breg.y;
            sBf[buf][ks][nt][ln+2][bb] = breg.z;
            sBf[buf][ks][nt][ln+3][bb] = breg.w;
        }
        if (tid < MT) sAdj[buf][tid] = aw;
        __syncthreads();

        if (chunk < 31) {
            int n = tid >> 3, k4 = tid & 7;
            breg = *(const float4*)(BT + (long long)n*NN + (chunk+1)*32 + k4*4);
            if (tid < MT) aw = adjTp[(long long)(chunk+1)*NN];
        }

        unsigned wr[2];
        wr[0] = sAdj[buf][wl*16 + g];
        wr[1] = sAdj[buf][wl*16 + g + 8];

#pragma unroll
        for (int s = 0; s < 4; s++) {
            const float4 gva = sGv[chunk*32 + 8*s + t];
            const float4 gvb = sGv[chunk*32 + 8*s + t + 4];
            uint32_t afr[4];
#pragma unroll
            for (int half = 0; half < 2; half++) {
                float s0 = fr[half] + gva.x;
                float p0 = (s0 > 0.f ? ear[half] : ecr[half]) * (s0 > 0.f ? gva.y : gva.z);
                p0 = ((wr[half] >> (8*s + t)) & 1u) ? p0 : 0.f;
                float s1 = fr[half] + gvb.x;
                float p1 = (s1 > 0.f ? ear[half] : ecr[half]) * (s1 > 0.f ? gvb.y : gvb.z);
                p1 = ((wr[half] >> (8*s + t + 4)) & 1u) ? p1 : 0.f;
                afr[half]     = to_tf32_u(p0);
                afr[half + 2] = to_tf32_u(p1);
            }
#pragma unroll
            for (int j = 0; j < 2; j++) {
                uint32_t bf[2];
                float2 bv = *(const float2*)&sBf[buf][s][wg*2 + j][lane][0];
                bf[0] = __float_as_uint(bv.x); bf[1] = __float_as_uint(bv.y);
                mma_tf32_16x8x8(acc[j], afr, bf);
            }
            if (wg == 0) mma_tf32_16x8x8(accS, afr, bone);
        }
    }

    if (wg == 0 && t == 0) {
        sS[wl*16 + g]     = accS[0];
        sS[wl*16 + g + 8] = accS[2];
    }
    __syncthreads();

#pragma unroll
    for (int half = 0; half < 2; half++) {
        int lrow = wl*16 + g + 8*half;
        int grow = i0 + lrow;
        float isv = 1.0f / fmaxf(sS[lrow], 1e-30f);
#pragma unroll
        for (int j = 0; j < 2; j++) {
            float v0 = acc[j][half*2+0] * isv;
            float v1 = acc[j][half*2+1] * isv;
            float* o = dout + ((long long)(b*NN + grow))*NCLASS + (wg*2 + j)*8 + t*2;
            *(float2*)o = make_float2(v0, v1);
        }
    }
}

// ---------------- 5) whx2 via mma.sync: 256 thr, split-N warp groups ----------------
// grid 256, 8 warps = 2 groups of 4; group wg owns n-tiles {2wg, 2wg+1}.
// smem layout (flat, 11072 floats = 44.3 KB):
//   [0, 2176)      sHt: k*68 + r     (A tile; reused as sT after loop)
//   [2176, 10496)  sWoT: n*260 + k   (tf32 Wo transposed; frag LDS conflict-free)
//   [10496, 10752) sWaf  [10752, 11008) sWag  [11008, 11072) sAo
__global__ __launch_bounds__(256) void whx2_mma_kernel(const float* __restrict__ Wo,
                                                       const float* __restrict__ ao) {
    __shared__ float sm[11072];
    float* sWoT = sm + 2176;
    float* sWaf = sm + 10496;
    float* sWag = sm + 10752;
    float* sAo  = sm + 11008;

    const int tid = threadIdx.x, wid = tid >> 5, lane = tid & 31;
    const int g = lane >> 2, t = lane & 3;
    const int wg = wid >> 2, wl = wid & 3;
    const long long rowbase = (long long)blockIdx.x * 64;
    const int b = (int)(rowbase >> 10);
    const int j0 = (int)(rowbase & 1023);
    const float* hrow = d_hcat + rowbase * 256;

    if (tid < 64) sAo[tid] = ao[tid];
    for (int idx4 = tid; idx4 < 2048; idx4 += 256) {
        int row = idx4 >> 3, c4 = idx4 & 7;
        float4 v = *(const float4*)(Wo + row*NCLASS + c4*4);
        sWoT[(c4*4+0)*260 + row] = to_tf32(v.x);
        sWoT[(c4*4+1)*260 + row] = to_tf32(v.y);
        sWoT[(c4*4+2)*260 + row] = to_tf32(v.z);
        sWoT[(c4*4+3)*260 + row] = to_tf32(v.w);
    }
    __syncthreads();
    {   // waf/wag: one k per thread
        int k = tid;
        const float* wr = Wo + k*NCLASS;
        float f = 0.f, gg = 0.f;
#pragma unroll 8
        for (int c = 0; c < NCLASS; c++) { f += wr[c]*sAo[c]; gg += wr[c]*sAo[NCLASS+c]; }
        sWaf[k] = f; sWag[k] = gg;
    }

    float acc[2][4];
#pragma unroll
    for (int j = 0; j < 2; j++)
#pragma unroll
        for (int c = 0; c < 4; c++) acc[j][c] = 0.f;
    float pf[2] = {0.f, 0.f}, pg[2] = {0.f, 0.f};

    float4 areg[2];
#pragma unroll
    for (int q = 0; q < 2; q++) {
        int idx = tid + 256*q; int r = idx >> 3, c4 = idx & 7;
        areg[q] = *(const float4*)(hrow + (long long)r*256 + c4*4);
    }

#pragma unroll 1
    for (int kc = 0; kc < 8; kc++) {
#pragma unroll
        for (int q = 0; q < 2; q++) {
            int idx = tid + 256*q; int r = idx >> 3, c4 = idx & 7;
            sm[(c4*4+0)*68 + r] = areg[q].x;
            sm[(c4*4+1)*68 + r] = areg[q].y;
            sm[(c4*4+2)*68 + r] = areg[q].z;
            sm[(c4*4+3)*68 + r] = areg[q].w;
        }
        __syncthreads();
        if (kc < 7) {
#pragma unroll
            for (int q = 0; q < 2; q++) {
                int idx = tid + 256*q; int r = idx >> 3, c4 = idx & 7;
                areg[q] = *(const float4*)(hrow + (long long)r*256 + (kc+1)*32 + c4*4);
            }
        }
        uint32_t bfr[4][2][2];
#pragma unroll
        for (int s = 0; s < 4; s++) {
            int k0 = kc*32 + 8*s + t;
#pragma unroll
            for (int j = 0; j < 2; j++) {
                int n = (wg*2 + j)*8 + g;
                bfr[s][j][0] = __float_as_uint(sWoT[n*260 + k0]);
                bfr[s][j][1] = __float_as_uint(sWoT[n*260 + k0 + 4]);
            }
        }
#pragma unroll
        for (int s = 0; s < 4; s++) {
            int rg = wl*16 + g;
            float a0 = sm[(8*s + t)*68 + rg];
            float a1 = sm[(8*s + t)*68 + rg + 8];
            float a2 = sm[(8*s + t + 4)*68 + rg];
            float a3 = sm[(8*s + t + 4)*68 + rg + 8];
            uint32_t afr[4];
            afr[0] = to_tf32_u(a0); afr[1] = to_tf32_u(a1);
            afr[2] = to_tf32_u(a2); afr[3] = to_tf32_u(a3);
            if (wg == 0) {
                float wf0 = sWaf[kc*32 + 8*s + t], wf1 = sWaf[kc*32 + 8*s + t + 4];
                float wg0 = sWag[kc*32 + 8*s + t], wg1 = sWag[kc*32 + 8*s + t + 4];
                pf[0] += a0*wf0 + a2*wf1;  pf[1] += a1*wf0 + a3*wf1;
                pg[0] += a0*wg0 + a2*wg1;  pg[1] += a1*wg0 + a3*wg1;
            }
#pragma unroll
            for (int j = 0; j < 2; j++)
                mma_tf32_16x8x8(acc[j], afr, bfr[s][j]);
        }
        __syncthreads();
    }

    if (wg == 0) {
#pragma unroll
        for (int r = 0; r < 2; r++) {
            pf[r] += __shfl_xor_sync(FULL, pf[r], 1); pg[r] += __shfl_xor_sync(FULL, pg[r], 1);
            pf[r] += __shfl_xor_sync(FULL, pf[r], 2); pg[r] += __shfl_xor_sync(FULL, pg[r], 2);
        }
        if (t == 0) {
#pragma unroll
            for (int r = 0; r < 2; r++) {
                int o = (int)rowbase + wl*16 + g + 8*r;
                d_f2[o] = pf[r];
                d_eac2[o] = make_float2(__expf(pf[r]), __expf(LRA*pf[r]));
                d_gv2[o] = make_float4(pg[r], __expf(pg[r]), __expf(LRA*pg[r]), 0.f);
            }
        }
    }

    // Wh2T transpose staging (aliases sHt; loop's trailing sync passed)
#pragma unroll
    for (int j = 0; j < 2; j++)
#pragma unroll
        for (int c = 0; c < 4; c++) {
            int col = (wg*2 + j)*8 + t*2 + (c & 1);
            int lr = wl*16 + g + 8*(c >> 1);
            sm[col*68 + lr] = to_tf32(acc[j][c]);
        }
    __syncthreads();
    for (int idx = tid; idx < 32*16; idx += 256) {
        int c = idx >> 4, j4 = idx & 15;
        float4 v = make_float4(sm[c*68 + j4*4], sm[c*68 + j4*4+1],
                               sm[c*68 + j4*4+2], sm[c*68 + j4*4+3]);
        *(float4*)(d_Wh2T + ((long long)b*NCLASS + c)*NN + j0 + j4*4) = v;
    }
}

// ---------------- launch ----------------
extern "C" void kernel_launch(void* const* d_in, const int* in_sizes, int n_in,
                              void* d_out, int out_size) {
    (void)in_sizes; (void)n_in; (void)out_size;
    const float* x       = (const float*)d_in[0];
    const int*   adj     = (const int*)  d_in[1];
    const float* W_heads = (const float*)d_in[2];
    const float* a_heads = (const float*)d_in[3];
    const float* W_out   = (const float*)d_in[4];
    const float* a_out   = (const float*)d_in[5];
    float* out = (float*)d_out;

    pack_adj_kernel<<<BB*NN/8, 256>>>(adj);
    whx1_kernel<<<dim3(NN/64, BB, NHEADS), 256>>>(x, W_heads, a_heads);
    pv1_mma_kernel<<<dim3(NN/128, BB, NHEADS), 256>>>();
    whx2_mma_kernel<<<BB*NN/64, 256>>>(W_out, a_out);
    pv2_mma_kernel<<<dim3(NN/64, BB), 256>>>(out);
}

// round 16
// speedup vs baseline: 1.0341x; 1.0341x over previous
#include <cuda_runtime.h>
#include <math.h>
#include <stdint.h>

#define BB 16
#define NN 1024
#define NHEADS 4
#define FIN 64
#define NHID 64
#define NCLASS 32
#define LRA 0.2f
#define FULL 0xffffffffu

// ---------------- scratch (device globals; no allocs) ----------------
__device__ __align__(16) float d_Wh1T[NHEADS*BB*NHID*NN];  // [h,b][c][j] 16.8 MB (tf32)
__device__ float d_f1[NHEADS*BB*NN];
__device__ __align__(8)  float2 d_eac1[NHEADS*BB*NN];      // (e^f, e^{0.2f})
__device__ __align__(16) float4 d_gv1[NHEADS*BB*NN];       // (g, e^g, e^{0.2g}, 0)
__device__ __align__(16) float d_hcat[BB*NN*NHEADS*NHID];  // 16.8 MB
__device__ __align__(16) float d_Wh2T[BB*NCLASS*NN];       // [b][c][j] 2 MB (tf32)
__device__ float d_f2[BB*NN];
__device__ __align__(8)  float2 d_eac2[BB*NN];
__device__ __align__(16) float4 d_gv2[BB*NN];
__device__ unsigned d_adjT[BB*(NN/32)*NN];   // [b][word][i]  2 MB

__device__ __forceinline__ float to_tf32(float x) {
    uint32_t r; asm("cvt.rna.tf32.f32 %0, %1;" : "=r"(r) : "f"(x));
    return __uint_as_float(r);
}
__device__ __forceinline__ uint32_t to_tf32_u(float x) {
    uint32_t r; asm("cvt.rna.tf32.f32 %0, %1;" : "=r"(r) : "f"(x));
    return r;
}
__device__ __forceinline__ void mma_tf32_16x8x8(float* d, const uint32_t* a, const uint32_t* b) {
    asm volatile(
        "mma.sync.aligned.m16n8k8.row.col.f32.tf32.tf32.f32 "
        "{%0,%1,%2,%3}, {%4,%5,%6,%7}, {%8,%9}, {%0,%1,%2,%3};"
        : "+f"(d[0]), "+f"(d[1]), "+f"(d[2]), "+f"(d[3])
        : "r"(a[0]), "r"(a[1]), "r"(a[2]), "r"(a[3]), "r"(b[0]), "r"(b[1]));
}

// ---------------- 1) pack adjacency to transposed bitmask ----------------
__global__ void pack_adj_kernel(const int* __restrict__ adj) {
    int warp = (blockIdx.x * blockDim.x + threadIdx.x) >> 5;
    int lane = threadIdx.x & 31;
    if (warp >= BB*NN) return;
    const int* row = adj + (long long)warp * NN;
    int b = warp >> 10, i = warp & 1023;
    unsigned mym = 0;
#pragma unroll
    for (int wb = 0; wb < 4; wb++) {
        int v[8];
#pragma unroll
        for (int u = 0; u < 8; u++) v[u] = row[(wb*8 + u)*32 + lane];
#pragma unroll
        for (int u = 0; u < 8; u++) {
            unsigned m = __ballot_sync(FULL, v[u] > 0);
            if (lane == wb*8 + u) mym = m;
        }
    }
    d_adjT[(b*32 + lane)*NN + i] = mym;
}

// ---------------- 2) Wh1T = (x @ W_heads[h])^T;  f,g + exps ----------------
// grid (NN/64, BB, NHEADS), block 256
__global__ void whx1_kernel(const float* __restrict__ x,
                            const float* __restrict__ Wh,
                            const float* __restrict__ ah) {
    __shared__ __align__(16) float sW[FIN*NHID];   // 16 KB
    __shared__ float sX[64][FIN+1];                // 16.6 KB; reused as transpose buffer
    __shared__ float sA[2*NHID];
    int h = blockIdx.z, b = blockIdx.y, i0 = blockIdx.x*64;
    int tid = threadIdx.x;

    const float4* Wsrc = (const float4*)(Wh + (long long)h*FIN*NHID);
    float4* Wdst = (float4*)sW;
    for (int idx = tid; idx < FIN*NHID/4; idx += 256) Wdst[idx] = Wsrc[idx];
    if (tid < 2*NHID) sA[tid] = ah[h*2*NHID + tid];
    for (int idx = tid; idx < 64*FIN/4; idx += 256) {
        int r = idx >> 4, c4 = idx & 15;
        float4 v = *(const float4*)(x + (long long)(b*NN + i0 + r)*FIN + c4*4);
        sX[r][c4*4+0]=v.x; sX[r][c4*4+1]=v.y; sX[r][c4*4+2]=v.z; sX[r][c4*4+3]=v.w;
    }
    __syncthreads();

    int r = tid >> 2, ct = tid & 3, c0 = ct*16;
    float acc[16];
#pragma unroll
    for (int c = 0; c < 16; c++) acc[c] = 0.f;
#pragma unroll 4
    for (int k = 0; k < FIN; k++) {
        float xv = sX[r][k];
#pragma unroll
        for (int c4 = 0; c4 < 4; c4++) {
            float4 w = *(const float4*)(&sW[k*NHID + c0 + c4*4]);
            acc[c4*4+0] += xv*w.x; acc[c4*4+1] += xv*w.y;
            acc[c4*4+2] += xv*w.z; acc[c4*4+3] += xv*w.w;
        }
    }

    float pf = 0.f, pg = 0.f;
#pragma unroll
    for (int c = 0; c < 16; c++) { pf += acc[c]*sA[c0+c]; pg += acc[c]*sA[NHID+c0+c]; }
    pf += __shfl_xor_sync(FULL, pf, 1); pg += __shfl_xor_sync(FULL, pg, 1);
    pf += __shfl_xor_sync(FULL, pf, 2); pg += __shfl_xor_sync(FULL, pg, 2);
    if (ct == 0) {
        int o = (h*BB+b)*NN + i0 + r;
        d_f1[o] = pf;
        d_eac1[o] = make_float2(__expf(pf), __expf(LRA*pf));
        d_gv1[o] = make_float4(pg, __expf(pg), __expf(LRA*pg), 0.f);
    }

    __syncthreads();
#pragma unroll
    for (int c = 0; c < 16; c++) sX[c0 + c][r] = to_tf32(acc[c]);
    __syncthreads();
    float* WT = d_Wh1T + (long long)(h*BB + b)*NHID*NN;
    for (int idx = tid; idx < 64*16; idx += 256) {
        int c = idx >> 4, j4 = idx & 15;
        float4 v = make_float4(sX[c][j4*4], sX[c][j4*4+1], sX[c][j4*4+2], sX[c][j4*4+3]);
        *(float4*)(WT + (long long)c*NN + i0 + j4*4) = v;
    }
}

// ---------------- 3) PV via mma.sync tf32 + ones-column row sums ----------------
// LAYER1: M-tile 128, 256 thr (8 warps x 16 rows). LAYER2: M-tile 64, 128 thr.
template<int LAYER>
__global__ __launch_bounds__((LAYER == 1) ? 256 : 128)
void pv_mma_kernel(float* __restrict__ dout) {
    constexpr int F    = (LAYER == 1) ? NHID : NCLASS;
    constexpr int MT   = (LAYER == 1) ? 128 : 64;
    constexpr int NTHR = (MT/16) * 32;
    constexpr int NT   = F / 8;
    constexpr int NQ   = (32*F/4) / NTHR;               // = 2
    __shared__ float4 sGv[NN];
    __shared__ float  sF[MT];
    __shared__ float2 sEac[MT];
    __shared__ float  sBf[2][4][NT][32][2];
    __shared__ unsigned sAdj[2][MT];
    __shared__ float  sS[MT];

    const int tid = threadIdx.x, wid = tid >> 5, lane = tid & 31;
    const int g = lane >> 2, t = lane & 3;
    const int b = blockIdx.y, h = blockIdx.z, i0 = blockIdx.x * MT;
    const int hb = (LAYER == 1) ? (h*BB + b) : b;
    const float*  fA  = (LAYER == 1) ? d_f1  : d_f2;
    const float2* eac = (LAYER == 1) ? d_eac1 : d_eac2;
    const float4* gvA = (LAYER == 1) ? d_gv1 : d_gv2;
    const float*  BT  = (LAYER == 1) ? (d_Wh1T + (long long)hb*F*NN)
                                     : (d_Wh2T + (long long)b*F*NN);

    for (int idx = tid; idx < NN; idx += NTHR) sGv[idx] = gvA[(long long)hb*NN + idx];
    if (tid < MT) {
        sF[tid]   = fA[(long long)hb*NN + i0 + tid];
        sEac[tid] = eac[(long long)hb*NN + i0 + tid];
    }
    __syncthreads();

    float fr[2], ear[2], ecr[2];
#pragma unroll
    for (int r = 0; r < 2; r++) {
        int lr = wid*16 + g + 8*r;
        fr[r] = sF[lr]; ear[r] = sEac[lr].x; ecr[r] = sEac[lr].y;
    }

    float acc[NT][4], accS[4];
#pragma unroll
    for (int nt = 0; nt < NT; nt++)
#pragma unroll
        for (int c = 0; c < 4; c++) acc[nt][c] = 0.f;
#pragma unroll
    for (int c = 0; c < 4; c++) accS[c] = 0.f;
    uint32_t bone[2];
    bone[0] = bone[1] = (lane < 4) ? 0x3f800000u : 0u;

    const unsigned* adjTp = d_adjT + (long long)b*32*NN + i0 + tid;

    float4 breg[NQ];
#pragma unroll
    for (int q = 0; q < NQ; q++) {
        int idx = tid + NTHR*q; int n = idx >> 3, k4 = idx & 7;
        breg[q] = *(const float4*)(BT + (long long)n*NN + k4*4);
    }
    unsigned aw = (tid < MT) ? adjTp[0] : 0u;

#pragma unroll 1
    for (int chunk = 0; chunk < 32; chunk++) {
        const int buf = chunk & 1;
#pragma unroll
        for (int q = 0; q < NQ; q++) {
            int idx = tid + NTHR*q; int n = idx >> 3, k4 = idx & 7;
            int ks = k4 >> 1, bb = k4 & 1, nt = n >> 3, ln = (n & 7) * 4;
            sBf[buf][ks][nt][ln+0][bb] = breg[q].x;
            sBf[buf][ks][nt][ln+1][bb] = breg[q].y;
            sBf[buf][ks][nt][ln+2][bb] = breg[q].z;
            sBf[buf][ks][nt][ln+3][bb] = breg[q].w;
        }
        if (tid < MT) sAdj[buf][tid] = aw;
        __syncthreads();

        if (chunk < 31) {
#pragma unroll
            for (int q = 0; q < NQ; q++) {
                int idx = tid + NTHR*q; int n = idx >> 3, k4 = idx & 7;
                breg[q] = *(const float4*)(BT + (long long)n*NN + (chunk+1)*32 + k4*4);
            }
            if (tid < MT) aw = adjTp[(long long)(chunk+1)*NN];
        }

        unsigned wr[2];
        wr[0] = sAdj[buf][wid*16 + g];
        wr[1] = sAdj[buf][wid*16 + g + 8];

#pragma unroll
        for (int s = 0; s < 4; s++) {
            const float4 gva = sGv[chunk*32 + 8*s + t];
            const float4 gvb = sGv[chunk*32 + 8*s + t + 4];
            uint32_t afr[4];
#pragma unroll
            for (int half = 0; half < 2; half++) {
                float s0 = fr[half] + gva.x;
                float p0 = (s0 > 0.f ? ear[half] : ecr[half]) * (s0 > 0.f ? gva.y : gva.z);
                p0 = ((wr[half] >> (8*s + t)) & 1u) ? p0 : 0.f;
                float s1 = fr[half] + gvb.x;
                float p1 = (s1 > 0.f ? ear[half] : ecr[half]) * (s1 > 0.f ? gvb.y : gvb.z);
                p1 = ((wr[half] >> (8*s + t + 4)) & 1u) ? p1 : 0.f;
                afr[half]     = to_tf32_u(p0);
                afr[half + 2] = to_tf32_u(p1);
            }
#pragma unroll
            for (int nt = 0; nt < NT; nt++) {
                uint32_t bf[2];
                float2 bv = *(const float2*)&sBf[buf][s][nt][lane][0];
                bf[0] = __float_as_uint(bv.x); bf[1] = __float_as_uint(bv.y);
                mma_tf32_16x8x8(acc[nt], afr, bf);
            }
            mma_tf32_16x8x8(accS, afr, bone);
        }
    }

    if (t == 0) {
        sS[wid*16 + g]     = accS[0];
        sS[wid*16 + g + 8] = accS[2];
    }
    __syncthreads();

#pragma unroll
    for (int half = 0; half < 2; half++) {
        int lrow = wid*16 + g + 8*half;
        int grow = i0 + lrow;
        float isv = 1.0f / fmaxf(sS[lrow], 1e-30f);
#pragma unroll
        for (int nt = 0; nt < NT; nt++) {
            float v0 = acc[nt][half*2+0] * isv;
            float v1 = acc[nt][half*2+1] * isv;
            if (LAYER == 1) {
                v0 = v0 > 0.f ? v0 : expm1f(v0);
                v1 = v1 > 0.f ? v1 : expm1f(v1);
                float* o = d_hcat + ((long long)(b*NN + grow))*(NHEADS*NHID) + h*NHID + nt*8 + t*2;
                *(float2*)o = make_float2(v0, v1);
            } else {
                float* o = dout + ((long long)(b*NN + grow))*NCLASS + nt*8 + t*2;
                *(float2*)o = make_float2(v0, v1);
            }
        }
    }
}

// ---------------- 4) whx2 via mma.sync: 256 thr, split-N warp groups ----------------
// grid 256, 8 warps = 2 groups of 4; group wg owns n-tiles {2wg, 2wg+1}.
// smem layout (flat, 11072 floats = 44.3 KB):
//   [0, 2176)      sHt: k*68 + r     (A tile; reused as sT after loop)
//   [2176, 10496)  sWoT: n*260 + k   (tf32 Wo transposed; frag LDS conflict-free)
//   [10496, 10752) sWaf  [10752, 11008) sWag  [11008, 11072) sAo
__global__ __launch_bounds__(256) void whx2_mma_kernel(const float* __restrict__ Wo,
                                                       const float* __restrict__ ao) {
    __shared__ float sm[11072];
    float* sWoT = sm + 2176;
    float* sWaf = sm + 10496;
    float* sWag = sm + 10752;
    float* sAo  = sm + 11008;

    const int tid = threadIdx.x, wid = tid >> 5, lane = tid & 31;
    const int g = lane >> 2, t = lane & 3;
    const int wg = wid >> 2, wl = wid & 3;
    const long long rowbase = (long long)blockIdx.x * 64;
    const int b = (int)(rowbase >> 10);
    const int j0 = (int)(rowbase & 1023);
    const float* hrow = d_hcat + rowbase * 256;

    if (tid < 64) sAo[tid] = ao[tid];
    for (int idx4 = tid; idx4 < 2048; idx4 += 256) {
        int row = idx4 >> 3, c4 = idx4 & 7;
        float4 v = *(const float4*)(Wo + row*NCLASS + c4*4);
        sWoT[(c4*4+0)*260 + row] = to_tf32(v.x);
        sWoT[(c4*4+1)*260 + row] = to_tf32(v.y);
        sWoT[(c4*4+2)*260 + row] = to_tf32(v.z);
        sWoT[(c4*4+3)*260 + row] = to_tf32(v.w);
    }
    __syncthreads();
    {   // waf/wag: one k per thread
        int k = tid;
        const float* wr = Wo + k*NCLASS;
        float f = 0.f, gg = 0.f;
#pragma unroll 8
        for (int c = 0; c < NCLASS; c++) { f += wr[c]*sAo[c]; gg += wr[c]*sAo[NCLASS+c]; }
        sWaf[k] = f; sWag[k] = gg;
    }

    float acc[2][4];
#pragma unroll
    for (int j = 0; j < 2; j++)
#pragma unroll
        for (int c = 0; c < 4; c++) acc[j][c] = 0.f;
    float pf[2] = {0.f, 0.f}, pg[2] = {0.f, 0.f};

    float4 areg[2];
#pragma unroll
    for (int q = 0; q < 2; q++) {
        int idx = tid + 256*q; int r = idx >> 3, c4 = idx & 7;
        areg[q] = *(const float4*)(hrow + (long long)r*256 + c4*4);
    }

#pragma unroll 1
    for (int kc = 0; kc < 8; kc++) {
#pragma unroll
        for (int q = 0; q < 2; q++) {
            int idx = tid + 256*q; int r = idx >> 3, c4 = idx & 7;
            sm[(c4*4+0)*68 + r] = areg[q].x;
            sm[(c4*4+1)*68 + r] = areg[q].y;
            sm[(c4*4+2)*68 + r] = areg[q].z;
            sm[(c4*4+3)*68 + r] = areg[q].w;
        }
        __syncthreads();
        if (kc < 7) {
#pragma unroll
            for (int q = 0; q < 2; q++) {
                int idx = tid + 256*q; int r = idx >> 3, c4 = idx & 7;
                areg[q] = *(const float4*)(hrow + (long long)r*256 + (kc+1)*32 + c4*4);
            }
        }
        uint32_t bfr[4][2][2];
#pragma unroll
        for (int s = 0; s < 4; s++) {
            int k0 = kc*32 + 8*s + t;
#pragma unroll
            for (int j = 0; j < 2; j++) {
                int n = (wg*2 + j)*8 + g;
                bfr[s][j][0] = __float_as_uint(sWoT[n*260 + k0]);
                bfr[s][j][1] = __float_as_uint(sWoT[n*260 + k0 + 4]);
            }
        }
#pragma unroll
        for (int s = 0; s < 4; s++) {
            int rg = wl*16 + g;
            float a0 = sm[(8*s + t)*68 + rg];
            float a1 = sm[(8*s + t)*68 + rg + 8];
            float a2 = sm[(8*s + t + 4)*68 + rg];
            float a3 = sm[(8*s + t + 4)*68 + rg + 8];
            uint32_t afr[4];
            afr[0] = to_tf32_u(a0); afr[1] = to_tf32_u(a1);
            afr[2] = to_tf32_u(a2); afr[3] = to_tf32_u(a3);
            if (wg == 0) {
                float wf0 = sWaf[kc*32 + 8*s + t], wf1 = sWaf[kc*32 + 8*s + t + 4];
                float wg0 = sWag[kc*32 + 8*s + t], wg1 = sWag[kc*32 + 8*s + t + 4];
                pf[0] += a0*wf0 + a2*wf1;  pf[1] += a1*wf0 + a3*wf1;
                pg[0] += a0*wg0 + a2*wg1;  pg[1] += a1*wg0 + a3*wg1;
            }
#pragma unroll
            for (int j = 0; j < 2; j++)
                mma_tf32_16x8x8(acc[j], afr, bfr[s][j]);
        }
        __syncthreads();
    }

    if (wg == 0) {
#pragma unroll
        for (int r = 0; r < 2; r++) {
            pf[r] += __shfl_xor_sync(FULL, pf[r], 1); pg[r] += __shfl_xor_sync(FULL, pg[r], 1);
            pf[r] += __shfl_xor_sync(FULL, pf[r], 2); pg[r] += __shfl_xor_sync(FULL, pg[r], 2);
        }
        if (t == 0) {
#pragma unroll
            for (int r = 0; r < 2; r++) {
                int o = (int)rowbase + wl*16 + g + 8*r;
                d_f2[o] = pf[r];
                d_eac2[o] = make_float2(__expf(pf[r]), __expf(LRA*pf[r]));
                d_gv2[o] = make_float4(pg[r], __expf(pg[r]), __expf(LRA*pg[r]), 0.f);
            }
        }
    }

    // Wh2T transpose staging (aliases sHt; loop's trailing sync passed)
#pragma unroll
    for (int j = 0; j < 2; j++)
#pragma unroll
        for (int c = 0; c < 4; c++) {
            int col = (wg*2 + j)*8 + t*2 + (c & 1);
            int lr = wl*16 + g + 8*(c >> 1);
            sm[col*68 + lr] = to_tf32(acc[j][c]);
        }
    __syncthreads();
    for (int idx = tid; idx < 32*16; idx += 256) {
        int c = idx >> 4, j4 = idx & 15;
        float4 v = make_float4(sm[c*68 + j4*4], sm[c*68 + j4*4+1],
                               sm[c*68 + j4*4+2], sm[c*68 + j4*4+3]);
        *(float4*)(d_Wh2T + ((long long)b*NCLASS + c)*NN + j0 + j4*4) = v;
    }
}

// ---------------- launch ----------------
extern "C" void kernel_launch(void* const* d_in, const int* in_sizes, int n_in,
                              void* d_out, int out_size) {
    (void)in_sizes; (void)n_in; (void)out_size;
    const float* x       = (const float*)d_in[0];
    const int*   adj     = (const int*)  d_in[1];
    const float* W_heads = (const float*)d_in[2];
    const float* a_heads = (const float*)d_in[3];
    const float* W_out   = (const float*)d_in[4];
    const float* a_out   = (const float*)d_in[5];
    float* out = (float*)d_out;

    pack_adj_kernel<<<BB*NN/8, 256>>>(adj);
    whx1_kernel<<<dim3(NN/64, BB, NHEADS), 256>>>(x, W_heads, a_heads);
    pv_mma_kernel<1><<<dim3(NN/128, BB, NHEADS), 256>>>(nullptr);
    whx2_mma_kernel<<<BB*NN/64, 256>>>(W_out, a_out);
    pv_mma_kernel<2><<<dim3(NN/64, BB, 1), 128>>>(out);
}

// round 17
// speedup vs baseline: 1.0707x; 1.0354x over previous
#include <cuda_runtime.h>
#include <math.h>
#include <stdint.h>

#define BB 16
#define NN 1024
#define NHEADS 4
#define FIN 64
#define NHID 64
#define NCLASS 32
#define LRA 0.2f
#define FULL 0xffffffffu

// ---------------- scratch (device globals; no allocs) ----------------
__device__ __align__(16) float d_Wh1T[NHEADS*BB*NHID*NN];  // [h,b][c][j] 16.8 MB (tf32)
__device__ __align__(8)  float2 d_eac1[NHEADS*BB*NN];      // (e^f, e^{0.2f})
__device__ __align__(8)  float2 d_gv1[NHEADS*BB*NN];       // (e^g, e^{0.2g})
__device__ __align__(16) float d_hcat[BB*NN*NHEADS*NHID];  // 16.8 MB
__device__ __align__(16) float d_Wh2T[BB*NCLASS*NN];       // [b][c][j] 2 MB (tf32)
__device__ __align__(8)  float2 d_eac2[BB*NN];
__device__ __align__(8)  float2 d_gv2[BB*NN];
__device__ unsigned d_adjT[BB*(NN/32)*NN];   // [b][word][i]  2 MB

__device__ __forceinline__ float to_tf32(float x) {
    uint32_t r; asm("cvt.rna.tf32.f32 %0, %1;" : "=r"(r) : "f"(x));
    return __uint_as_float(r);
}
__device__ __forceinline__ uint32_t to_tf32_u(float x) {
    uint32_t r; asm("cvt.rna.tf32.f32 %0, %1;" : "=r"(r) : "f"(x));
    return r;
}
__device__ __forceinline__ void mma_tf32_16x8x8(float* d, const uint32_t* a, const uint32_t* b) {
    asm volatile(
        "mma.sync.aligned.m16n8k8.row.col.f32.tf32.tf32.f32 "
        "{%0,%1,%2,%3}, {%4,%5,%6,%7}, {%8,%9}, {%0,%1,%2,%3};"
        : "+f"(d[0]), "+f"(d[1]), "+f"(d[2]), "+f"(d[3])
        : "r"(a[0]), "r"(a[1]), "r"(a[2]), "r"(a[3]), "r"(b[0]), "r"(b[1]));
}

// ---------------- 1) pack adjacency to transposed bitmask ----------------
__global__ void pack_adj_kernel(const int* __restrict__ adj) {
    int warp = (blockIdx.x * blockDim.x + threadIdx.x) >> 5;
    int lane = threadIdx.x & 31;
    if (warp >= BB*NN) return;
    const int* row = adj + (long long)warp * NN;
    int b = warp >> 10, i = warp & 1023;
    unsigned mym = 0;
#pragma unroll
    for (int wb = 0; wb < 4; wb++) {
        int v[8];
#pragma unroll
        for (int u = 0; u < 8; u++) v[u] = row[(wb*8 + u)*32 + lane];
#pragma unroll
        for (int u = 0; u < 8; u++) {
            unsigned m = __ballot_sync(FULL, v[u] > 0);
            if (lane == wb*8 + u) mym = m;
        }
    }
    d_adjT[(b*32 + lane)*NN + i] = mym;
}

// ---------------- 2) Wh1T = (x @ W_heads[h])^T;  exps of f,g ----------------
// grid (NN/64, BB, NHEADS), block 256
__global__ void whx1_kernel(const float* __restrict__ x,
                            const float* __restrict__ Wh,
                            const float* __restrict__ ah) {
    __shared__ __align__(16) float sW[FIN*NHID];   // 16 KB
    __shared__ float sX[64][FIN+1];                // 16.6 KB; reused as transpose buffer
    __shared__ float sA[2*NHID];
    int h = blockIdx.z, b = blockIdx.y, i0 = blockIdx.x*64;
    int tid = threadIdx.x;

    const float4* Wsrc = (const float4*)(Wh + (long long)h*FIN*NHID);
    float4* Wdst = (float4*)sW;
    for (int idx = tid; idx < FIN*NHID/4; idx += 256) Wdst[idx] = Wsrc[idx];
    if (tid < 2*NHID) sA[tid] = ah[h*2*NHID + tid];
    for (int idx = tid; idx < 64*FIN/4; idx += 256) {
        int r = idx >> 4, c4 = idx & 15;
        float4 v = *(const float4*)(x + (long long)(b*NN + i0 + r)*FIN + c4*4);
        sX[r][c4*4+0]=v.x; sX[r][c4*4+1]=v.y; sX[r][c4*4+2]=v.z; sX[r][c4*4+3]=v.w;
    }
    __syncthreads();

    int r = tid >> 2, ct = tid & 3, c0 = ct*16;
    float acc[16];
#pragma unroll
    for (int c = 0; c < 16; c++) acc[c] = 0.f;
#pragma unroll 4
    for (int k = 0; k < FIN; k++) {
        float xv = sX[r][k];
#pragma unroll
        for (int c4 = 0; c4 < 4; c4++) {
            float4 w = *(const float4*)(&sW[k*NHID + c0 + c4*4]);
            acc[c4*4+0] += xv*w.x; acc[c4*4+1] += xv*w.y;
            acc[c4*4+2] += xv*w.z; acc[c4*4+3] += xv*w.w;
        }
    }

    float pf = 0.f, pg = 0.f;
#pragma unroll
    for (int c = 0; c < 16; c++) { pf += acc[c]*sA[c0+c]; pg += acc[c]*sA[NHID+c0+c]; }
    pf += __shfl_xor_sync(FULL, pf, 1); pg += __shfl_xor_sync(FULL, pg, 1);
    pf += __shfl_xor_sync(FULL, pf, 2); pg += __shfl_xor_sync(FULL, pg, 2);
    if (ct == 0) {
        int o = (h*BB+b)*NN + i0 + r;
        d_eac1[o] = make_float2(__expf(pf), __expf(LRA*pf));
        d_gv1[o]  = make_float2(__expf(pg), __expf(LRA*pg));
    }

    __syncthreads();
#pragma unroll
    for (int c = 0; c < 16; c++) sX[c0 + c][r] = to_tf32(acc[c]);
    __syncthreads();
    float* WT = d_Wh1T + (long long)(h*BB + b)*NHID*NN;
    for (int idx = tid; idx < 64*16; idx += 256) {
        int c = idx >> 4, j4 = idx & 15;
        float4 v = make_float4(sX[c][j4*4], sX[c][j4*4+1], sX[c][j4*4+2], sX[c][j4*4+3]);
        *(float4*)(WT + (long long)c*NN + i0 + j4*4) = v;
    }
}

// ---------------- 3) PV via mma.sync tf32 + ones-column row sums ----------------
// p = max(e^f e^g, e^{0.2f} e^{0.2g})  [= exp(lrelu(f+g)) since lrelu(x)=max(x,0.2x)]
// LAYER1: M-tile 128, 256 thr. LAYER2: M-tile 64, 128 thr.
template<int LAYER>
__global__ __launch_bounds__((LAYER == 1) ? 256 : 128)
void pv_mma_kernel(float* __restrict__ dout) {
    constexpr int F    = (LAYER == 1) ? NHID : NCLASS;
    constexpr int MT   = (LAYER == 1) ? 128 : 64;
    constexpr int NTHR = (MT/16) * 32;
    constexpr int NT   = F / 8;
    constexpr int NQ   = (32*F/4) / NTHR;               // = 2
    __shared__ float2 sGv[NN];                          // 8 KB
    __shared__ float2 sEac[MT];
    __shared__ float  sBf[2][4][NT][32][2];
    __shared__ unsigned sAdj[2][MT];
    __shared__ float  sS[MT];

    const int tid = threadIdx.x, wid = tid >> 5, lane = tid & 31;
    const int g = lane >> 2, t = lane & 3;
    const int b = blockIdx.y, h = blockIdx.z, i0 = blockIdx.x * MT;
    const int hb = (LAYER == 1) ? (h*BB + b) : b;
    const float2* eac = (LAYER == 1) ? d_eac1 : d_eac2;
    const float2* gvA = (LAYER == 1) ? d_gv1 : d_gv2;
    const float*  BT  = (LAYER == 1) ? (d_Wh1T + (long long)hb*F*NN)
                                     : (d_Wh2T + (long long)b*F*NN);

    for (int idx = tid; idx < NN; idx += NTHR) sGv[idx] = gvA[(long long)hb*NN + idx];
    if (tid < MT) sEac[tid] = eac[(long long)hb*NN + i0 + tid];
    __syncthreads();

    float ear[2], ecr[2];
#pragma unroll
    for (int r = 0; r < 2; r++) {
        int lr = wid*16 + g + 8*r;
        ear[r] = sEac[lr].x; ecr[r] = sEac[lr].y;
    }

    float acc[NT][4], accS[4];
#pragma unroll
    for (int nt = 0; nt < NT; nt++)
#pragma unroll
        for (int c = 0; c < 4; c++) acc[nt][c] = 0.f;
#pragma unroll
    for (int c = 0; c < 4; c++) accS[c] = 0.f;
    uint32_t bone[2];
    bone[0] = bone[1] = (lane < 4) ? 0x3f800000u : 0u;

    const unsigned* adjTp = d_adjT + (long long)b*32*NN + i0 + tid;

    float4 breg[NQ];
#pragma unroll
    for (int q = 0; q < NQ; q++) {
        int idx = tid + NTHR*q; int n = idx >> 3, k4 = idx & 7;
        breg[q] = *(const float4*)(BT + (long long)n*NN + k4*4);
    }
    unsigned aw = (tid < MT) ? adjTp[0] : 0u;

#pragma unroll 1
    for (int chunk = 0; chunk < 32; chunk++) {
        const int buf = chunk & 1;
#pragma unroll
        for (int q = 0; q < NQ; q++) {
            int idx = tid + NTHR*q; int n = idx >> 3, k4 = idx & 7;
            int ks = k4 >> 1, bb = k4 & 1, nt = n >> 3, ln = (n & 7) * 4;
            sBf[buf][ks][nt][ln+0][bb] = breg[q].x;
            sBf[buf][ks][nt][ln+1][bb] = breg[q].y;
            sBf[buf][ks][nt][ln+2][bb] = breg[q].z;
            sBf[buf][ks][nt][ln+3][bb] = breg[q].w;
        }
        if (tid < MT) sAdj[buf][tid] = aw;
        __syncthreads();

        if (chunk < 31) {
#pragma unroll
            for (int q = 0; q < NQ; q++) {
                int idx = tid + NTHR*q; int n = idx >> 3, k4 = idx & 7;
                breg[q] = *(const float4*)(BT + (long long)n*NN + (chunk+1)*32 + k4*4);
            }
            if (tid < MT) aw = adjTp[(long long)(chunk+1)*NN];
        }

        unsigned wr[2];
        wr[0] = sAdj[buf][wid*16 + g];
        wr[1] = sAdj[buf][wid*16 + g + 8];

#pragma unroll
        for (int s = 0; s < 4; s++) {
            const float2 gva = sGv[chunk*32 + 8*s + t];
            const float2 gvb = sGv[chunk*32 + 8*s + t + 4];
            uint32_t afr[4];
#pragma unroll
            for (int half = 0; half < 2; half++) {
                float p0 = fmaxf(ear[half]*gva.x, ecr[half]*gva.y);
                p0 = ((wr[half] >> (8*s + t)) & 1u) ? p0 : 0.f;
                float p1 = fmaxf(ear[half]*gvb.x, ecr[half]*gvb.y);
                p1 = ((wr[half] >> (8*s + t + 4)) & 1u) ? p1 : 0.f;
                afr[half]     = to_tf32_u(p0);
                afr[half + 2] = to_tf32_u(p1);
            }
#pragma unroll
            for (int nt = 0; nt < NT; nt++) {
                uint32_t bf[2];
                float2 bv = *(const float2*)&sBf[buf][s][nt][lane][0];
                bf[0] = __float_as_uint(bv.x); bf[1] = __float_as_uint(bv.y);
                mma_tf32_16x8x8(acc[nt], afr, bf);
            }
            mma_tf32_16x8x8(accS, afr, bone);
        }
    }

    if (t == 0) {
        sS[wid*16 + g]     = accS[0];
        sS[wid*16 + g + 8] = accS[2];
    }
    __syncthreads();

#pragma unroll
    for (int half = 0; half < 2; half++) {
        int lrow = wid*16 + g + 8*half;
        int grow = i0 + lrow;
        float isv = 1.0f / fmaxf(sS[lrow], 1e-30f);
#pragma unroll
        for (int nt = 0; nt < NT; nt++) {
            float v0 = acc[nt][half*2+0] * isv;
            float v1 = acc[nt][half*2+1] * isv;
            if (LAYER == 1) {
                v0 = v0 > 0.f ? v0 : expm1f(v0);
                v1 = v1 > 0.f ? v1 : expm1f(v1);
                float* o = d_hcat + ((long long)(b*NN + grow))*(NHEADS*NHID) + h*NHID + nt*8 + t*2;
                *(float2*)o = make_float2(v0, v1);
            } else {
                float* o = dout + ((long long)(b*NN + grow))*NCLASS + nt*8 + t*2;
                *(float2*)o = make_float2(v0, v1);
            }
        }
    }
}

// ---------------- 4) whx2 via mma.sync: 256 thr, split-N warp groups ----------------
// grid 256, 8 warps = 2 groups of 4; group wg owns n-tiles {2wg, 2wg+1}.
// smem layout (flat, 11072 floats = 44.3 KB):
//   [0, 2176)      sHt: k*68 + r     (A tile; reused as sT after loop)
//   [2176, 10496)  sWoT: n*260 + k   (tf32 Wo transposed)
//   [10496, 10752) sWaf  [10752, 11008) sWag  [11008, 11072) sAo
__global__ __launch_bounds__(256) void whx2_mma_kernel(const float* __restrict__ Wo,
                                                       const float* __restrict__ ao) {
    __shared__ float sm[11072];
    float* sWoT = sm + 2176;
    float* sWaf = sm + 10496;
    float* sWag = sm + 10752;
    float* sAo  = sm + 11008;

    const int tid = threadIdx.x, wid = tid >> 5, lane = tid & 31;
    const int g = lane >> 2, t = lane & 3;
    const int wg = wid >> 2, wl = wid & 3;
    const long long rowbase = (long long)blockIdx.x * 64;
    const int b = (int)(rowbase >> 10);
    const int j0 = (int)(rowbase & 1023);
    const float* hrow = d_hcat + rowbase * 256;

    if (tid < 64) sAo[tid] = ao[tid];
    for (int idx4 = tid; idx4 < 2048; idx4 += 256) {
        int row = idx4 >> 3, c4 = idx4 & 7;
        float4 v = *(const float4*)(Wo + row*NCLASS + c4*4);
        sWoT[(c4*4+0)*260 + row] = to_tf32(v.x);
        sWoT[(c4*4+1)*260 + row] = to_tf32(v.y);
        sWoT[(c4*4+2)*260 + row] = to_tf32(v.z);
        sWoT[(c4*4+3)*260 + row] = to_tf32(v.w);
    }
    __syncthreads();
    {   // waf/wag: one k per thread
        int k = tid;
        const float* wr = Wo + k*NCLASS;
        float f = 0.f, gg = 0.f;
#pragma unroll 8
        for (int c = 0; c < NCLASS; c++) { f += wr[c]*sAo[c]; gg += wr[c]*sAo[NCLASS+c]; }
        sWaf[k] = f; sWag[k] = gg;
    }

    float acc[2][4];
#pragma unroll
    for (int j = 0; j < 2; j++)
#pragma unroll
        for (int c = 0; c < 4; c++) acc[j][c] = 0.f;
    float pf[2] = {0.f, 0.f}, pg[2] = {0.f, 0.f};

    float4 areg[2];
#pragma unroll
    for (int q = 0; q < 2; q++) {
        int idx = tid + 256*q; int r = idx >> 3, c4 = idx & 7;
        areg[q] = *(const float4*)(hrow + (long long)r*256 + c4*4);
    }

#pragma unroll 1
    for (int kc = 0; kc < 8; kc++) {
#pragma unroll
        for (int q = 0; q < 2; q++) {
            int idx = tid + 256*q; int r = idx >> 3, c4 = idx & 7;
            sm[(c4*4+0)*68 + r] = areg[q].x;
            sm[(c4*4+1)*68 + r] = areg[q].y;
            sm[(c4*4+2)*68 + r] = areg[q].z;
            sm[(c4*4+3)*68 + r] = areg[q].w;
        }
        __syncthreads();
        if (kc < 7) {
#pragma unroll
            for (int q = 0; q < 2; q++) {
                int idx = tid + 256*q; int r = idx >> 3, c4 = idx & 7;
                areg[q] = *(const float4*)(hrow + (long long)r*256 + (kc+1)*32 + c4*4);
            }
        }
        uint32_t bfr[4][2][2];
#pragma unroll
        for (int s = 0; s < 4; s++) {
            int k0 = kc*32 + 8*s + t;
#pragma unroll
            for (int j = 0; j < 2; j++) {
                int n = (wg*2 + j)*8 + g;
                bfr[s][j][0] = __float_as_uint(sWoT[n*260 + k0]);
                bfr[s][j][1] = __float_as_uint(sWoT[n*260 + k0 + 4]);
            }
        }
#pragma unroll
        for (int s = 0; s < 4; s++) {
            int rg = wl*16 + g;
            float a0 = sm[(8*s + t)*68 + rg];
            float a1 = sm[(8*s + t)*68 + rg + 8];
            float a2 = sm[(8*s + t + 4)*68 + rg];
            float a3 = sm[(8*s + t + 4)*68 + rg + 8];
            uint32_t afr[4];
            afr[0] = to_tf32_u(a0); afr[1] = to_tf32_u(a1);
            afr[2] = to_tf32_u(a2); afr[3] = to_tf32_u(a3);
            if (wg == 0) {
                float wf0 = sWaf[kc*32 + 8*s + t], wf1 = sWaf[kc*32 + 8*s + t + 4];
                float wg0 = sWag[kc*32 + 8*s + t], wg1 = sWag[kc*32 + 8*s + t + 4];
                pf[0] += a0*wf0 + a2*wf1;  pf[1] += a1*wf0 + a3*wf1;
                pg[0] += a0*wg0 + a2*wg1;  pg[1] += a1*wg0 + a3*wg1;
            }
#pragma unroll
            for (int j = 0; j < 2; j++)
                mma_tf32_16x8x8(acc[j], afr, bfr[s][j]);
        }
        __syncthreads();
    }

    if (wg == 0) {
#pragma unroll
        for (int r = 0; r < 2; r++) {
            pf[r] += __shfl_xor_sync(FULL, pf[r], 1); pg[r] += __shfl_xor_sync(FULL, pg[r], 1);
            pf[r] += __shfl_xor_sync(FULL, pf[r], 2); pg[r] += __shfl_xor_sync(FULL, pg[r], 2);
        }
        if (t == 0) {
#pragma unroll
            for (int r = 0; r < 2; r++) {
                int o = (int)rowbase + wl*16 + g + 8*r;
                d_eac2[o] = make_float2(__expf(pf[r]), __expf(LRA*pf[r]));
                d_gv2[o]  = make_float2(__expf(pg[r]), __expf(LRA*pg[r]));
            }
        }
    }

    // Wh2T transpose staging (aliases sHt; loop's trailing sync passed)
#pragma unroll
    for (int j = 0; j < 2; j++)
#pragma unroll
        for (int c = 0; c < 4; c++) {
            int col = (wg*2 + j)*8 + t*2 + (c & 1);
            int lr = wl*16 + g + 8*(c >> 1);
            sm[col*68 + lr] = to_tf32(acc[j][c]);
        }
    __syncthreads();
    for (int idx = tid; idx < 32*16; idx += 256) {
        int c = idx >> 4, j4 = idx & 15;
        float4 v = make_float4(sm[c*68 + j4*4], sm[c*68 + j4*4+1],
                               sm[c*68 + j4*4+2], sm[c*68 + j4*4+3]);
        *(float4*)(d_Wh2T + ((long long)b*NCLASS + c)*NN + j0 + j4*4) = v;
    }
}

// ---------------- launch ----------------
extern "C" void kernel_launch(void* const* d_in, const int* in_sizes, int n_in,
                              void* d_out, int out_size) {
    (void)in_sizes; (void)n_in; (void)out_size;
    const float* x       = (const float*)d_in[0];
    const int*   adj     = (const int*)  d_in[1];
    const float* W_heads = (const float*)d_in[2];
    const float* a_heads = (const float*)d_in[3];
    const float* W_out   = (const float*)d_in[4];
    const float* a_out   = (const float*)d_in[5];
    float* out = (float*)d_out;

    pack_adj_kernel<<<BB*NN/8, 256>>>(adj);
    whx1_kernel<<<dim3(NN/64, BB, NHEADS), 256>>>(x, W_heads, a_heads);
    pv_mma_kernel<1><<<dim3(NN/128, BB, NHEADS), 256>>>(nullptr);
    whx2_mma_kernel<<<BB*NN/64, 256>>>(W_out, a_out);
    pv_mma_kernel<2><<<dim3(NN/64, BB, 1), 128>>>(out);
}